// round 10
// baseline (speedup 1.0000x reference)
#include <cuda_runtime.h>

#define N_PATHS 1000000
#define N_LINKS 50000
#define K_HOPS  8
#define N_REP   16

// Scratch: __device__ globals. Zero-init at module load; link_update re-zeroes
// g_T each pass, so "g_T == 0 on entry" is an invariant across graph replays.
// g_bp is written by the first link_update before its first read (pass 1 is
// specialized to bp == 0.5).
__device__ float g_T[N_REP][N_LINKS];
__device__ float g_bp[N_LINKS];
__device__ float g_Xl[N_LINKS];

// A = P[:,1] for 4 consecutive paths via 3 float4 loads (3*p0 % 4 == 0).
__device__ __forceinline__ void load_A4(const float* __restrict__ P, int p0,
                                        float& t0, float& t1, float& t2, float& t3) {
    const float4* P4 = reinterpret_cast<const float4*>(P + 3 * p0);
    float4 a = __ldg(&P4[0]);
    float4 b = __ldg(&P4[1]);
    float4 c = __ldg(&P4[2]);
    t0 = a.y; t1 = b.x; t2 = b.w; t3 = c.z;
}

// Pass 1: bp == 0.5 -> t_k = A[p] * 0.5^k. No gathers, no dep chain; pure
// scatter throughput -> 8 paths/thread (validated win in R6 re-attribution).
__global__ void __launch_bounds__(128) traffic_pass1_kernel(const float* __restrict__ P,
                                                            const int*   __restrict__ edges) {
    int g = blockIdx.x * blockDim.x + threadIdx.x;
    if (g >= N_PATHS / 8) return;
    int p0 = g * 8;
    float* __restrict__ T = g_T[threadIdx.x & (N_REP - 1)];

    float t0, t1, t2, t3, t4, t5, t6, t7;
    load_A4(P, p0,     t0, t1, t2, t3);
    load_A4(P, p0 + 4, t4, t5, t6, t7);

#pragma unroll
    for (int k = 0; k < K_HOPS; k++) {
        const int* ek = edges + (size_t)k * N_PATHS + p0;
        int4 a4 = *reinterpret_cast<const int4*>(ek);
        int4 b4 = *reinterpret_cast<const int4*>(ek + 4);
        atomicAdd(&T[a4.x - N_PATHS], t0);
        atomicAdd(&T[a4.y - N_PATHS], t1);
        atomicAdd(&T[a4.z - N_PATHS], t2);
        atomicAdd(&T[a4.w - N_PATHS], t3);
        atomicAdd(&T[b4.x - N_PATHS], t4);
        atomicAdd(&T[b4.y - N_PATHS], t5);
        atomicAdd(&T[b4.z - N_PATHS], t6);
        atomicAdd(&T[b4.w - N_PATHS], t7);
        t0 *= 0.5f; t1 *= 0.5f; t2 *= 0.5f; t3 *= 0.5f;
        t4 *= 0.5f; t5 *= 0.5f; t6 *= 0.5f; t7 *= 0.5f;
    }
}

// Passes 2/3 (best-known form, unchanged): T[e] += t (RED into one of 16
// replicas), then t *= (1 - bp[e]); bp (200KB) stays L1-resident.
__global__ void __launch_bounds__(128) traffic_kernel(const float* __restrict__ P,
                                                      const int*   __restrict__ edges) {
    int p0 = (blockIdx.x * blockDim.x + threadIdx.x) * 4;
    if (p0 >= N_PATHS) return;
    float* __restrict__ T = g_T[threadIdx.x & (N_REP - 1)];

    float t0, t1, t2, t3;
    load_A4(P, p0, t0, t1, t2, t3);

#pragma unroll
    for (int k = 0; k < K_HOPS; k++) {
        int4 e4 = *reinterpret_cast<const int4*>(edges + (size_t)k * N_PATHS + p0);
        int e0 = e4.x - N_PATHS;
        int e1 = e4.y - N_PATHS;
        int e2 = e4.z - N_PATHS;
        int e3 = e4.w - N_PATHS;

        atomicAdd(&T[e0], t0);
        atomicAdd(&T[e1], t1);
        atomicAdd(&T[e2], t2);
        atomicAdd(&T[e3], t3);

        t0 *= 1.0f - __ldg(&g_bp[e0]);
        t1 *= 1.0f - __ldg(&g_bp[e1]);
        t2 *= 1.0f - __ldg(&g_bp[e2]);
        t3 *= 1.0f - __ldg(&g_bp[e3]);
    }
}

// Link update: one thread per link, coalesced replica loads (measured-best form).
__global__ void __launch_bounds__(256) link_update_kernel(const float* __restrict__ L) {
    int l = blockIdx.x * blockDim.x + threadIdx.x;
    if (l >= N_LINKS) return;

    float Tl = 0.0f;
#pragma unroll
    for (int r = 0; r < N_REP; r++) {
        Tl += g_T[r][l];
        g_T[r][l] = 0.0f;
    }

    float rho = Tl / (__ldg(&L[l]) / 1000.0f);
    float r2 = rho * rho, r4 = r2 * r2, r8 = r4 * r4, r16 = r8 * r8, r32 = r16 * r16;
    g_bp[l] = (1.0f - rho) * r32 / (1.0f - r32 * rho + 1e-8f);
}

// Final link update (iteration 3) fused with the per-link epilogue.
__global__ void __launch_bounds__(256) link_update_final_kernel(const float* __restrict__ L,
                                                                float* __restrict__ out) {
    int l = blockIdx.x * blockDim.x + threadIdx.x;
    if (l >= N_LINKS) return;

    float Tl = 0.0f;
#pragma unroll
    for (int r = 0; r < N_REP; r++) {
        Tl += g_T[r][l];
        g_T[r][l] = 0.0f;
    }

    float Lraw = __ldg(&L[l]);
    float rho  = Tl / (Lraw / 1000.0f);

    float r2 = rho * rho, r4 = r2 * r2, r8 = r4 * r4, r16 = r8 * r8, r32 = r16 * r16;
    float r33 = r32 * rho;
    float pi0 = (1.0f - rho) / (1.0f - r33);

    float s = 1.0f, pw = 1.0f;
#pragma unroll
    for (int m = 1; m <= 32; m++) { pw *= rho; s += (float)m * pw; }

    float Lq   = pi0 * s / 32.0f;
    float pi0f = pi0 * r32;
    float Xl   = Lq * 32000.0f / Lraw;

    g_Xl[l] = Xl;

    out[N_PATHS + 3 * l + 0] = Lq;
    out[N_PATHS + 3 * l + 1] = rho;
    out[N_PATHS + 3 * l + 2] = pi0f;
}

// res[p] = sum_k X_l[e[k,p]]; no atomics, no dep chain -> 8 paths/thread
// (validated win in R6 re-attribution). X_l (200KB) L1-resident.
__global__ void __launch_bounds__(128) final_path_kernel(const int* __restrict__ edges,
                                                         float* __restrict__ out) {
    int g = blockIdx.x * blockDim.x + threadIdx.x;
    if (g >= N_PATHS / 8) return;
    int p0 = g * 8;

    float s0 = 0.f, s1 = 0.f, s2 = 0.f, s3 = 0.f;
    float s4 = 0.f, s5 = 0.f, s6 = 0.f, s7 = 0.f;
#pragma unroll
    for (int k = 0; k < K_HOPS; k++) {
        const int* ek = edges + (size_t)k * N_PATHS + p0;
        int4 a4 = *reinterpret_cast<const int4*>(ek);
        int4 b4 = *reinterpret_cast<const int4*>(ek + 4);
        s0 += __ldg(&g_Xl[a4.x - N_PATHS]);
        s1 += __ldg(&g_Xl[a4.y - N_PATHS]);
        s2 += __ldg(&g_Xl[a4.z - N_PATHS]);
        s3 += __ldg(&g_Xl[a4.w - N_PATHS]);
        s4 += __ldg(&g_Xl[b4.x - N_PATHS]);
        s5 += __ldg(&g_Xl[b4.y - N_PATHS]);
        s6 += __ldg(&g_Xl[b4.z - N_PATHS]);
        s7 += __ldg(&g_Xl[b4.w - N_PATHS]);
    }
    *reinterpret_cast<float4*>(out + p0)     = make_float4(s0, s1, s2, s3);
    *reinterpret_cast<float4*>(out + p0 + 4) = make_float4(s4, s5, s6, s7);
}

extern "C" void kernel_launch(void* const* d_in, const int* in_sizes, int n_in,
                              void* d_out, int out_size) {
    const float* P     = (const float*)d_in[0];   // (N_PATHS, 3)
    const float* L     = (const float*)d_in[1];   // (N_LINKS, 1)
    // d_in[2] = pl_paths: identity, unused
    const int*   edges = (const int*)d_in[3];     // (K_HOPS, N_PATHS)
    float* out = (float*)d_out;

    const int LB  = (N_LINKS + 255) / 256;        // 196 CTAs
    const int PB4 = (N_PATHS / 4 + 127) / 128;    // 1954 CTAs
    const int PB8 = (N_PATHS / 8 + 127) / 128;    //  977 CTAs

    traffic_pass1_kernel<<<PB8, 128>>>(P, edges);   // bp == 0.5 exactly
    link_update_kernel<<<LB, 256>>>(L);

    traffic_kernel<<<PB4, 128>>>(P, edges);
    link_update_kernel<<<LB, 256>>>(L);

    traffic_kernel<<<PB4, 128>>>(P, edges);
    link_update_final_kernel<<<LB, 256>>>(L, out);

    final_path_kernel<<<PB8, 128>>>(edges, out);
}

// round 11
// speedup vs baseline: 1.0263x; 1.0263x over previous
#include <cuda_runtime.h>

#define N_PATHS 1000000
#define N_LINKS 50000
#define K_HOPS  8
#define N_REP   16

// Scratch: __device__ globals. Zero-init at module load; link_update re-zeroes
// g_T each pass, so "g_T == 0 on entry" is an invariant across graph replays.
// g_bp is written by the first link_update before its first read (pass 1 is
// specialized to bp == 0.5).
__device__ float g_T[N_REP][N_LINKS];
__device__ float g_bp[N_LINKS];
__device__ float g_Xl[N_LINKS];

// A = P[:,1] for 4 consecutive paths via 3 float4 loads (3*p0 % 4 == 0).
__device__ __forceinline__ void load_A4(const float* __restrict__ P, int p0,
                                        float& t0, float& t1, float& t2, float& t3) {
    const float4* P4 = reinterpret_cast<const float4*>(P + 3 * p0);
    float4 a = __ldg(&P4[0]);
    float4 b = __ldg(&P4[1]);
    float4 c = __ldg(&P4[2]);
    t0 = a.y; t1 = b.x; t2 = b.w; t3 = c.z;
}

// Pass 1: bp == 0.5 -> t_k = A[p] * 0.5^k. No gathers. (156.1us-validated form.)
__global__ void __launch_bounds__(128) traffic_pass1_kernel(const float* __restrict__ P,
                                                            const int*   __restrict__ edges) {
    int p0 = (blockIdx.x * blockDim.x + threadIdx.x) * 4;
    if (p0 >= N_PATHS) return;
    float* __restrict__ T = g_T[threadIdx.x & (N_REP - 1)];

    float t0, t1, t2, t3;
    load_A4(P, p0, t0, t1, t2, t3);

#pragma unroll
    for (int k = 0; k < K_HOPS; k++) {
        int4 e4 = *reinterpret_cast<const int4*>(edges + (size_t)k * N_PATHS + p0);
        atomicAdd(&T[e4.x - N_PATHS], t0);
        atomicAdd(&T[e4.y - N_PATHS], t1);
        atomicAdd(&T[e4.z - N_PATHS], t2);
        atomicAdd(&T[e4.w - N_PATHS], t3);
        t0 *= 0.5f; t1 *= 0.5f; t2 *= 0.5f; t3 *= 0.5f;
    }
}

// Passes 2/3, MLP-restructured: (1) load all edges, (2) issue all 32 bp
// gathers (independent -> deep MLP, no serial gather chain), (3) FMA prefix
// products + 32 atomics. bp (200KB) stays L1-resident.
__global__ void __launch_bounds__(128) traffic_kernel(const float* __restrict__ P,
                                                      const int*   __restrict__ edges) {
    int p0 = (blockIdx.x * blockDim.x + threadIdx.x) * 4;
    if (p0 >= N_PATHS) return;
    float* __restrict__ T = g_T[threadIdx.x & (N_REP - 1)];

    float t0, t1, t2, t3;
    load_A4(P, p0, t0, t1, t2, t3);

    // Phase 1: all edge indices (8 independent int4 loads), pre-adjusted.
    int ex[K_HOPS], ey[K_HOPS], ez[K_HOPS], ew[K_HOPS];
#pragma unroll
    for (int k = 0; k < K_HOPS; k++) {
        int4 e4 = *reinterpret_cast<const int4*>(edges + (size_t)k * N_PATHS + p0);
        ex[k] = e4.x - N_PATHS;
        ey[k] = e4.y - N_PATHS;
        ez[k] = e4.z - N_PATHS;
        ew[k] = e4.w - N_PATHS;
    }

    // Phase 2: all 32 bp gathers, fully independent (32 outstanding loads).
    float bx[K_HOPS], by[K_HOPS], bz[K_HOPS], bw[K_HOPS];
#pragma unroll
    for (int k = 0; k < K_HOPS; k++) {
        bx[k] = __ldg(&g_bp[ex[k]]);
        by[k] = __ldg(&g_bp[ey[k]]);
        bz[k] = __ldg(&g_bp[ez[k]]);
        bw[k] = __ldg(&g_bp[ew[k]]);
    }

    // Phase 3: prefix products (FMA-only chain) + atomics (no return value).
#pragma unroll
    for (int k = 0; k < K_HOPS; k++) {
        atomicAdd(&T[ex[k]], t0);
        atomicAdd(&T[ey[k]], t1);
        atomicAdd(&T[ez[k]], t2);
        atomicAdd(&T[ew[k]], t3);
        t0 *= 1.0f - bx[k];
        t1 *= 1.0f - by[k];
        t2 *= 1.0f - bz[k];
        t3 *= 1.0f - bw[k];
    }
}

// Link update: one thread per link, coalesced replica loads (measured-best form).
__global__ void __launch_bounds__(256) link_update_kernel(const float* __restrict__ L) {
    int l = blockIdx.x * blockDim.x + threadIdx.x;
    if (l >= N_LINKS) return;

    float Tl = 0.0f;
#pragma unroll
    for (int r = 0; r < N_REP; r++) {
        Tl += g_T[r][l];
        g_T[r][l] = 0.0f;
    }

    float rho = Tl / (__ldg(&L[l]) / 1000.0f);
    float r2 = rho * rho, r4 = r2 * r2, r8 = r4 * r4, r16 = r8 * r8, r32 = r16 * r16;
    g_bp[l] = (1.0f - rho) * r32 / (1.0f - r32 * rho + 1e-8f);
}

// Final link update (iteration 3) fused with the per-link epilogue.
__global__ void __launch_bounds__(256) link_update_final_kernel(const float* __restrict__ L,
                                                                float* __restrict__ out) {
    int l = blockIdx.x * blockDim.x + threadIdx.x;
    if (l >= N_LINKS) return;

    float Tl = 0.0f;
#pragma unroll
    for (int r = 0; r < N_REP; r++) {
        Tl += g_T[r][l];
        g_T[r][l] = 0.0f;
    }

    float Lraw = __ldg(&L[l]);
    float rho  = Tl / (Lraw / 1000.0f);

    float r2 = rho * rho, r4 = r2 * r2, r8 = r4 * r4, r16 = r8 * r8, r32 = r16 * r16;
    float r33 = r32 * rho;
    float pi0 = (1.0f - rho) / (1.0f - r33);

    float s = 1.0f, pw = 1.0f;
#pragma unroll
    for (int m = 1; m <= 32; m++) { pw *= rho; s += (float)m * pw; }

    float Lq   = pi0 * s / 32.0f;
    float pi0f = pi0 * r32;
    float Xl   = Lq * 32000.0f / Lraw;

    g_Xl[l] = Xl;

    out[N_PATHS + 3 * l + 0] = Lq;
    out[N_PATHS + 3 * l + 1] = rho;
    out[N_PATHS + 3 * l + 2] = pi0f;
}

// res[p] = sum_k X_l[e[k,p]] (identity segment ids); X_l L1-resident.
// (156.1us-validated ILP-4 form.)
__global__ void __launch_bounds__(128) final_path_kernel(const int* __restrict__ edges,
                                                         float* __restrict__ out) {
    int p0 = (blockIdx.x * blockDim.x + threadIdx.x) * 4;
    if (p0 >= N_PATHS) return;

    float s0 = 0.f, s1 = 0.f, s2 = 0.f, s3 = 0.f;
#pragma unroll
    for (int k = 0; k < K_HOPS; k++) {
        int4 e4 = *reinterpret_cast<const int4*>(edges + (size_t)k * N_PATHS + p0);
        s0 += __ldg(&g_Xl[e4.x - N_PATHS]);
        s1 += __ldg(&g_Xl[e4.y - N_PATHS]);
        s2 += __ldg(&g_Xl[e4.z - N_PATHS]);
        s3 += __ldg(&g_Xl[e4.w - N_PATHS]);
    }
    *reinterpret_cast<float4*>(out + p0) = make_float4(s0, s1, s2, s3);
}

extern "C" void kernel_launch(void* const* d_in, const int* in_sizes, int n_in,
                              void* d_out, int out_size) {
    const float* P     = (const float*)d_in[0];   // (N_PATHS, 3)
    const float* L     = (const float*)d_in[1];   // (N_LINKS, 1)
    // d_in[2] = pl_paths: identity, unused
    const int*   edges = (const int*)d_in[3];     // (K_HOPS, N_PATHS)
    float* out = (float*)d_out;

    const int LB  = (N_LINKS + 255) / 256;        // 196 CTAs
    const int PB4 = (N_PATHS / 4 + 127) / 128;    // 1954 CTAs

    traffic_pass1_kernel<<<PB4, 128>>>(P, edges);   // bp == 0.5 exactly
    link_update_kernel<<<LB, 256>>>(L);

    traffic_kernel<<<PB4, 128>>>(P, edges);
    link_update_kernel<<<LB, 256>>>(L);

    traffic_kernel<<<PB4, 128>>>(P, edges);
    link_update_final_kernel<<<LB, 256>>>(L, out);

    final_path_kernel<<<PB4, 128>>>(edges, out);
}